// round 14
// baseline (speedup 1.0000x reference)
#include <cuda_runtime.h>

// ---------------------------------------------------------------------------
// 6-qubit, 3-layer circuit, B=131072. TWO threads per state (t = q0), each
// holding 16 packed-f32x2 real + 16 imag regs (lane = q5; pack bits
// 3..0 = q1,q2,q3,q4).
//  * Layer-1 CNOT ring + its q0,q1 gates absorbed analytically into build.
//  * Layer-1 q2..q5 gates: local packed butterflies.
//  * Layer 2: C01 = t-predicated SELs; C12/C23/C34 renames; C45+C50 folded
//    into the cross-thread q0-gate gather (partner xor 1); q1..q5 local.
//  * Layer 3: C01 SELs + C12/C23/C34 renames; C45, C50 and all six gates
//    absorbed into observables (Heisenberg).
//  Round 14: live-range restructuring (interleaved build tail; phased
//  measurement with immediate scalar reduction) + __launch_bounds__(128,6).
// ---------------------------------------------------------------------------

typedef unsigned long long u64;
#define SGN2 0x8000000080000000ULL

__device__ __forceinline__ u64 pk2(float a, float b) {
    u64 r; asm("mov.b64 %0,{%1,%2};" : "=l"(r) : "f"(a), "f"(b)); return r;
}
__device__ __forceinline__ void upk2(u64 v, float& a, float& b) {
    asm("mov.b64 {%0,%1},%2;" : "=f"(a), "=f"(b) : "l"(v));
}
__device__ __forceinline__ u64 bc2(float a) { return pk2(a, a); }
__device__ __forceinline__ u64 f2mul(u64 a, u64 b) {
    u64 d; asm("mul.rn.f32x2 %0,%1,%2;" : "=l"(d) : "l"(a), "l"(b)); return d;
}
__device__ __forceinline__ u64 f2fma(u64 a, u64 b, u64 c) {
    u64 d; asm("fma.rn.f32x2 %0,%1,%2,%3;" : "=l"(d) : "l"(a), "l"(b), "l"(c)); return d;
}
__device__ __forceinline__ u64 f2add(u64 a, u64 b) {
    u64 d; asm("add.rn.f32x2 %0,%1,%2;" : "=l"(d) : "l"(a), "l"(b)); return d;
}
__device__ __forceinline__ u64 f2swap(u64 a) {
    u64 d;
    asm("{\n\t.reg .b32 x,y;\n\tmov.b64 {x,y},%1;\n\tmov.b64 %0,{y,x};\n\t}"
        : "=l"(d) : "l"(a));
    return d;
}

// g_u[0..47]: layer-1 table (q2..q5 at slots 16..45).
// g_u[48..95]: layer-2 table: q0 at +0 [ar,ai,br,bi,-bi]; q1 at +8 and
//   q2..q4 at +16/+24/+32 [ar,ai,-ai,br,-br,bi,-bi]; q5 at +40.
__device__ u64 g_u[2 * 48];
// Layer-1 q0,q1 raw SU(2) coefficients
__device__ float g_l1[8];
// Observable combine constants per qubit: [cx, cy, cz, pad]
__device__ float g_m[24];

__global__ void prep_kernel(const float* __restrict__ theta) {
    int t = threadIdx.x;
    if (t < 18) {
        int l = t / 6, q = t % 6;
        const float* th = theta + t * 3;
        float sx, cx, sy, cy, sz, cz;
        __sincosf(th[0] * 0.5f, &sx, &cx);
        __sincosf(th[1] * 0.5f, &sy, &cy);
        __sincosf(th[2] * 0.5f, &sz, &cz);
        float m00r =  cy * cx, m00i =  sy * sx;
        float m01r = -sy * cx, m01i = -cy * sx;
        float ar = cz * m00r + sz * m00i, ai = cz * m00i - sz * m00r;
        float br = cz * m01r + sz * m01i, bi = cz * m01i - sz * m01r;
        if (l < 2) {
            u64* g = g_u + l * 48;
            if (q == 0) {
                if (l == 0) {
                    g_l1[0] = ar; g_l1[1] = ai; g_l1[2] = br; g_l1[3] = bi;
                } else {
                    g[0] = bc2(ar); g[1] = bc2(ai); g[2] = bc2(br);
                    g[3] = bc2(bi); g[4] = bc2(-bi);
                }
            } else if (q == 1) {
                if (l == 0) {
                    g_l1[4] = ar; g_l1[5] = ai; g_l1[6] = br; g_l1[7] = bi;
                } else {
                    u64* h = g + 8;
                    h[0] = bc2(ar); h[1] = bc2(ai); h[2] = bc2(-ai);
                    h[3] = bc2(br); h[4] = bc2(-br); h[5] = bc2(bi); h[6] = bc2(-bi);
                }
            } else if (q < 5) {
                u64* h = g + 16 + (q - 2) * 8;
                h[0] = bc2(ar); h[1] = bc2(ai); h[2] = bc2(-ai);
                h[3] = bc2(br); h[4] = bc2(-br); h[5] = bc2(bi); h[6] = bc2(-bi);
            } else {
                u64* h = g + 40;
                h[0] = pk2(ar, ar);   h[1] = pk2(-ai, ai);
                h[2] = pk2(br, -br);  h[3] = pk2(-bi, -bi);
                h[4] = pk2(ai, -ai);  h[5] = pk2(bi, bi);
            }
        } else {
            // layer 3 observable n-vector. even q: U†ZU, odd q: U†XU
            float nx, ny, nz;
            if ((q & 1) == 0) {
                nz = (ar * ar + ai * ai) - (br * br + bi * bi);
                nx = 2.0f * (br * ar + bi * ai);
                ny = 2.0f * (br * ai - bi * ar);
            } else {
                nz = -2.0f * (ar * br - ai * bi);
                nx = ar * ar - ai * ai - br * br + bi * bi;
                ny = 2.0f * (ar * ai + br * bi);
            }
            // fold 2x for single-sided pack-local cross sums
            if (q == 1 || q == 2 || q == 3) { nx *= 2.0f; ny *= 2.0f; }
            if (q == 4) { ny *= 2.0f; }
            g_m[q * 4 + 0] = nx;
            g_m[q * 4 + 1] = ny;
            g_m[q * 4 + 2] = nz;
        }
    }
}

// Local SU(2) on pack bit (MP = 8 -> q1, 4 -> q2, 2 -> q3, 1 -> q4).
template <int MP>
__device__ __forceinline__ void su2_loc(u64* R, u64* I, const u64* __restrict__ u) {
    u64 ar = u[0], ai = u[1], nai = u[2];
    u64 br = u[3], nbr = u[4], bi = u[5], nbi = u[6];
#pragma unroll
    for (int g = 0; g < 8; g++) {
        int p0 = (g & (MP - 1)) | ((g & ~(MP - 1)) << 1);
        int p1 = p0 | MP;
        u64 Ar = R[p0], Ai = I[p0], Br = R[p1], Bi = I[p1];
        R[p0] = f2fma(nbi, Bi, f2fma(br, Br, f2fma(nai, Ai, f2mul(ar, Ar))));
        I[p0] = f2fma(br, Bi, f2fma(bi, Br, f2fma(ai, Ar, f2mul(ar, Ai))));
        R[p1] = f2fma(ai, Bi, f2fma(ar, Br, f2fma(nbi, Ai, f2mul(nbr, Ar))));
        I[p1] = f2fma(nai, Br, f2fma(ar, Bi, f2fma(bi, Ar, f2mul(nbr, Ai))));
    }
}

// Local SU(2) on qubit 5 (lane), within-pack butterfly via half-swap.
__device__ __forceinline__ void su2_q5(u64* R, u64* I, const u64* __restrict__ u) {
    u64 aa = u[0], am = u[1], bp = u[2], nb2 = u[3], ap = u[4], bb = u[5];
#pragma unroll
    for (int p = 0; p < 16; p++) {
        u64 r = R[p], m = I[p];
        u64 sr = f2swap(r), sm = f2swap(m);
        R[p] = f2fma(nb2, sm, f2fma(bp, sr, f2fma(am, m, f2mul(aa, r))));
        I[p] = f2fma(bb, sr, f2fma(bp, sm, f2fma(ap, r, f2mul(aa, m))));
    }
}

__device__ __forceinline__ void swp(u64* A, int i, int j) {
    u64 t = A[i]; A[i] = A[j]; A[j] = t;
}

// CNOT(1,2),(2,3),(3,4) as register renames on the 16-pack array.
__device__ __forceinline__ void cnot_ring_mid(u64* R, u64* I) {
    swp(R, 8, 12); swp(R, 9, 13); swp(R, 10, 14); swp(R, 11, 15);
    swp(I, 8, 12); swp(I, 9, 13); swp(I, 10, 14); swp(I, 11, 15);
    swp(R, 4, 6); swp(R, 5, 7); swp(R, 12, 14); swp(R, 13, 15);
    swp(I, 4, 6); swp(I, 5, 7); swp(I, 12, 14); swp(I, 13, 15);
    swp(R, 2, 3); swp(R, 6, 7); swp(R, 10, 11); swp(R, 14, 15);
    swp(I, 2, 3); swp(I, 6, 7); swp(I, 10, 11); swp(I, 14, 15);
}

// CNOT(0,1): control = thread bit, target = pack bit3 (predicated SELs).
__device__ __forceinline__ void cnot01(u64* R, u64* I, bool c) {
#pragma unroll
    for (int p = 0; p < 8; p++) {
        u64 a = R[p], b = R[p + 8];
        R[p] = c ? b : a;  R[p + 8] = c ? a : b;
        a = I[p]; b = I[p + 8];
        I[p] = c ? b : a;  I[p + 8] = c ? a : b;
    }
}

__global__ __launch_bounds__(128, 6) void qsim_kernel(
    const float* __restrict__ x, float* __restrict__ out, int Bn)
{
    int gid = blockIdx.x * 128 + threadIdx.x;
    int st = gid >> 1;
    if (st >= Bn) return;
    int t = gid & 1;

    // --- encoding (1 sincos per qubit; double-angle for a/2 terms) ---
    const float4* x4 = reinterpret_cast<const float4*>(x) + (long)st * 6;
    float ur[6][2], ui[6][2];
#pragma unroll
    for (int q = 0; q < 6; q++) {
        float4 v = __ldg(&x4[q]);
        float a = (v.x + v.y + v.z + v.w) * 0.25f;
        a = fminf(6.0f, fmaxf(-6.0f, a)) * (3.14159265358979323846f / 6.0f);
        float s4, c4;
        __sincosf(a * 0.25f, &s4, &c4);
        float s2 = 2.0f * s4 * c4;
        float c2 = fmaf(-2.0f * s4, s4, 1.0f);
        ur[q][0] = c2 * c4;  ui[q][0] = -c2 * s4;
        ur[q][1] = s2 * s4;  ui[q][1] = -s2 * c4;
    }

    // --- build: U0 row t contracted; U1 expands pack bit3 (y1) ---
    float C0r, C0i, C1r, C1i;
    {
        float a0r = g_l1[0], a0i = g_l1[1], b0r = g_l1[2], b0i = g_l1[3];
        C0r = t ? -b0r : a0r;  C0i = t ?  b0i : a0i;
        C1r = t ?  a0r : b0r;  C1i = t ? -a0i : b0i;
    }
    float a1r = g_l1[4], a1i = g_l1[5], b1r = g_l1[6], b1i = g_l1[7];

    float Vr[2][2][2], Vi[2][2][2];  // [y1][y2][y5]
    {
        float Tr[2][2], Ti[2][2];  // [c0][y5]
#pragma unroll
        for (int y5 = 0; y5 < 2; y5++) {
            Tr[0][y5] = C0r * ur[0][y5] - C0i * ui[0][y5];
            Ti[0][y5] = C0r * ui[0][y5] + C0i * ur[0][y5];
            Tr[1][y5] = C1r * ur[0][1 ^ y5] - C1i * ui[0][1 ^ y5];
            Ti[1][y5] = C1r * ui[0][1 ^ y5] + C1i * ur[0][1 ^ y5];
        }
        float Wr[2][2], Wi[2][2];  // [c1][y5]
#pragma unroll
        for (int c1 = 0; c1 < 2; c1++)
#pragma unroll
            for (int y5 = 0; y5 < 2; y5++) {
                int j = c1 ^ y5;
                Wr[c1][y5] = Tr[0][y5] * ur[1][j] - Ti[0][y5] * ui[1][j]
                           + Tr[1][y5] * ur[1][j ^ 1] - Ti[1][y5] * ui[1][j ^ 1];
                Wi[c1][y5] = Tr[0][y5] * ui[1][j] + Ti[0][y5] * ur[1][j]
                           + Tr[1][y5] * ui[1][j ^ 1] + Ti[1][y5] * ur[1][j ^ 1];
            }
        // P[y1][c1][y5] = U1[y1,c1] * W[c1][y5];  U1 = [[a1,b1],[-b1*,a1*]]
        float Pr[2][2][2], Pi2[2][2][2];
#pragma unroll
        for (int y5 = 0; y5 < 2; y5++) {
            Pr[0][0][y5]  = a1r * Wr[0][y5] - a1i * Wi[0][y5];
            Pi2[0][0][y5] = a1r * Wi[0][y5] + a1i * Wr[0][y5];
            Pr[0][1][y5]  = b1r * Wr[1][y5] - b1i * Wi[1][y5];
            Pi2[0][1][y5] = b1r * Wi[1][y5] + b1i * Wr[1][y5];
            Pr[1][0][y5]  = -b1r * Wr[0][y5] - b1i * Wi[0][y5];
            Pi2[1][0][y5] = -b1r * Wi[0][y5] + b1i * Wr[0][y5];
            Pr[1][1][y5]  = a1r * Wr[1][y5] + a1i * Wi[1][y5];
            Pi2[1][1][y5] = a1r * Wi[1][y5] - a1i * Wr[1][y5];
        }
#pragma unroll
        for (int y1 = 0; y1 < 2; y1++)
#pragma unroll
            for (int y2 = 0; y2 < 2; y2++)
#pragma unroll
                for (int y5 = 0; y5 < 2; y5++) {
                    Vr[y1][y2][y5] =
                        Pr[y1][0][y5] * ur[2][y2] - Pi2[y1][0][y5] * ui[2][y2]
                      + Pr[y1][1][y5] * ur[2][y2 ^ 1] - Pi2[y1][1][y5] * ui[2][y2 ^ 1];
                    Vi[y1][y2][y5] =
                        Pr[y1][0][y5] * ui[2][y2] + Pi2[y1][0][y5] * ur[2][y2]
                      + Pr[y1][1][y5] * ui[2][y2 ^ 1] + Pi2[y1][1][y5] * ur[2][y2 ^ 1];
                }
    }

    // K tables (lane-packed): K[y3][y4] = u4[y4^y3] * u5[y4^y5]
    u64 R[16], I[16];
    {
        float k45r[2][2], k45i[2][2];
#pragma unroll
        for (int m = 0; m < 2; m++)
#pragma unroll
            for (int n = 0; n < 2; n++) {
                k45r[m][n] = ur[4][m] * ur[5][n] - ui[4][m] * ui[5][n];
                k45i[m][n] = ur[4][m] * ui[5][n] + ui[4][m] * ur[5][n];
            }
        u64 KR[2][2], KI[2][2];
#pragma unroll
        for (int y3 = 0; y3 < 2; y3++)
#pragma unroll
            for (int y4 = 0; y4 < 2; y4++) {
                int m = y4 ^ y3;
                KR[y3][y4] = pk2(k45r[m][y4], k45r[m][y4 ^ 1]);
                KI[y3][y4] = pk2(k45i[m][y4], k45i[m][y4 ^ 1]);
            }
        u64 w3r[2], w3i[2], n3i[2];
        w3r[0] = bc2(ur[3][0]); w3i[0] = bc2(ui[3][0]); n3i[0] = w3i[0] ^ SGN2;
        w3r[1] = bc2(ur[3][1]); w3i[1] = bc2(ui[3][1]); n3i[1] = w3i[1] ^ SGN2;

        // Interleaved tail: each (y1,y2,y3) chain entry is expanded to its two
        // packs immediately (no stored CRm array -> lower register peak).
#pragma unroll
        for (int y1 = 0; y1 < 2; y1++)
#pragma unroll
            for (int y2 = 0; y2 < 2; y2++) {
                u64 BR = pk2(Vr[y1][y2][0], Vr[y1][y2][1]);
                u64 BI = pk2(Vi[y1][y2][0], Vi[y1][y2][1]);
#pragma unroll
                for (int y3 = 0; y3 < 2; y3++) {
                    int m = y2 ^ y3;
                    u64 CR = f2fma(n3i[m], BI, f2mul(w3r[m], BR));
                    u64 CI = f2fma(w3i[m], BR, f2mul(w3r[m], BI));
#pragma unroll
                    for (int y4 = 0; y4 < 2; y4++) {
                        int p = (y1 << 3) | (y2 << 2) | (y3 << 1) | y4;
                        R[p] = f2fma(KI[y3][y4] ^ SGN2, CI, f2mul(KR[y3][y4], CR));
                        I[p] = f2fma(KI[y3][y4], CR, f2mul(KR[y3][y4], CI));
                    }
                }
            }
    }

    // --- layer-1 local gates (q2,q3,q4,q5) ---
    su2_loc<4>(R, I, g_u + 16);
    su2_loc<2>(R, I, g_u + 24);
    su2_loc<1>(R, I, g_u + 32);
    su2_q5(R, I, g_u + 40);

    // --- layer 2 (full) ---
    {
        const u64* cf = g_u + 48;
        cnot01(R, I, t != 0);
        cnot_ring_mid(R, I);

        // q0 gate (cross-thread, partner xor 1), C45 + C50 folded into gather.
        {
            u64 smask = t ? SGN2 : 0ULL;
            u64 car  = cf[0];
            u64 cai  = cf[1] ^ smask;
            u64 ncai = cai ^ SGN2;
            u64 cbr  = cf[2] ^ smask;
            u64 cbi  = cf[3];
            u64 ncbi = cf[4];
#pragma unroll
            for (int p = 0; p < 16; p++) {
                u64 LR = R[p], LI = I[p];
                u64 MR = __shfl_xor_sync(0xffffffffu, LR, 1);
                u64 MI = __shfl_xor_sync(0xffffffffu, LI, 1);
                float lr0, lr1, li0, li1, mr0, mr1, mi0, mi1;
                upk2(LR, lr0, lr1); upk2(LI, li0, li1);
                upk2(MR, mr0, mr1); upk2(MI, mi0, mi1);
                u64 AR, AI, BR, BI;
                if ((p & 1) == 0) {  // q4=0: C45 identity, C50 hi-lane cross
                    AR = pk2(lr0, mr1); AI = pk2(li0, mi1);
                    BR = pk2(mr0, lr1); BI = pk2(mi0, li1);
                } else {             // q4=1: C45 lane-swap then C50
                    AR = pk2(lr1, mr0); AI = pk2(li1, mi0);
                    BR = pk2(mr1, lr0); BI = pk2(mi1, li0);
                }
                R[p] = f2fma(ncbi, BI, f2fma(cbr, BR, f2fma(ncai, AI, f2mul(car, AR))));
                I[p] = f2fma(cbi, BR, f2fma(cbr, BI, f2fma(cai, AR, f2mul(car, AI))));
            }
        }

        su2_loc<8>(R, I, cf + 8);   // q1 (bit3)
        su2_loc<4>(R, I, cf + 16);  // q2 (bit2)
        su2_loc<2>(R, I, cf + 24);  // q3 (bit1)
        su2_loc<1>(R, I, cf + 32);  // q4 (bit0)
        su2_q5(R, I, cf + 40);      // q5 (lane)
    }

    // --- layer-3 prefix: C01 SEL + C12/C23/C34 renames; rest absorbed ---
    cnot01(R, I, t != 0);
    cnot_ring_mid(R, I);

    // --- measurements, phased to minimize live accumulators ---
    float lo, hi;

    // (a) probability pass: Z sums
    float sZ1, sZ2, sZ3, sZ4, sZ45;
    {
        u64 az1 = 0, az2 = 0, az3 = 0, az4 = 0;
#pragma unroll
        for (int p = 0; p < 16; p++) {
            u64 pr = f2fma(I[p], I[p], f2mul(R[p], R[p]));
            az1 = f2add(az1, (p & 8) ? (pr ^ SGN2) : pr);
            az2 = f2add(az2, (p & 4) ? (pr ^ SGN2) : pr);
            az3 = f2add(az3, (p & 2) ? (pr ^ SGN2) : pr);
            az4 = f2add(az4, (p & 1) ? (pr ^ SGN2) : pr);
        }
        upk2(az1, lo, hi); sZ1 = lo + hi;
        upk2(az2, lo, hi); sZ2 = lo + hi;
        upk2(az3, lo, hi); sZ3 = lo + hi;
        upk2(az4, lo, hi); sZ4 = lo + hi; sZ45 = lo - hi;
    }

    // (b) pack-local cross sums, one qubit at a time (2 accums live each)
    float sEx1, sEy1, sEx2, sEy2, sEx3, sEy3;
    {
        u64 e = 0, f = 0;
#pragma unroll
        for (int p = 0; p < 8; p++) {
            e = f2fma(R[p], R[p | 8], f2fma(I[p], I[p | 8], e));
            f = f2fma(R[p], I[p | 8], f2fma(I[p] ^ SGN2, R[p | 8], f));
        }
        upk2(e, lo, hi); sEx1 = lo + hi;
        upk2(f, lo, hi); sEy1 = lo + hi;
        e = 0; f = 0;
#pragma unroll
        for (int g = 0; g < 8; g++) {
            int p = (g & 3) | ((g & 4) << 1);  // 0..3, 8..11
            e = f2fma(R[p], R[p | 4], f2fma(I[p], I[p | 4], e));
            f = f2fma(R[p], I[p | 4], f2fma(I[p] ^ SGN2, R[p | 4], f));
        }
        upk2(e, lo, hi); sEx2 = lo + hi;
        upk2(f, lo, hi); sEy2 = lo + hi;
        e = 0; f = 0;
#pragma unroll
        for (int g = 0; g < 8; g++) {
            int p = (g & 1) | ((g & 6) << 1);  // 0,1,4,5,8,9,12,13
            e = f2fma(R[p], R[p | 2], f2fma(I[p], I[p | 2], e));
            f = f2fma(R[p], I[p | 2], f2fma(I[p] ^ SGN2, R[p | 2], f));
        }
        upk2(e, lo, hi); sEx3 = lo + hi;
        upk2(f, lo, hi); sEy3 = lo + hi;
    }

    // (c) q4/q5 coupled sums
    float sX45, sY45;
    {
        u64 x45 = 0, y45 = 0;
#pragma unroll
        for (int p = 0; p < 16; p++) {
            x45 = f2fma(R[p], f2swap(R[p ^ 1]), f2fma(I[p], f2swap(I[p ^ 1]), x45));
            if (!(p & 1)) {
                y45 = f2fma(R[p], f2swap(I[p | 1]),
                            f2fma(I[p] ^ SGN2, f2swap(R[p | 1]), y45));
            }
        }
        upk2(x45, lo, hi); sX45 = lo + hi;
        upk2(y45, lo, hi); sY45 = lo + hi;
    }

    // (d) cross-thread q0 observables (partner = lane xor 1)
    float sX0, sZY0, sX50, sZYX;
    {
        u64 ax0 = 0, zy0 = 0, x50 = 0, zyx = 0;
#pragma unroll
        for (int p = 0; p < 16; p++) {
            u64 PR = __shfl_xor_sync(0xffffffffu, R[p], 1);
            u64 PI = __shfl_xor_sync(0xffffffffu, I[p], 1);
            ax0 = f2fma(R[p], PR, f2fma(I[p], PI, ax0));
            {
                u64 v = f2fma(R[p], PI, f2mul(I[p] ^ SGN2, PR));
                zy0 = f2add(zy0, (p & 1) ? (v ^ SGN2) : v);
            }
            x50 = f2fma(R[p], f2swap(PR), f2fma(I[p], f2swap(PI), x50));
            {
                u64 v = f2fma(R[p], f2swap(PI), f2mul(I[p] ^ SGN2, f2swap(PR)));
                zyx = f2add(zyx, (p & 1) ? (v ^ SGN2) : v);
            }
        }
        upk2(ax0, lo, hi); sX0  = lo + hi;
        upk2(zy0, lo, hi); sZY0 = lo - hi;
        upk2(x50, lo, hi); sX50 = lo + hi;
        upk2(zyx, lo, hi); sZYX = lo - hi;
    }

    float sgT = t ? -1.0f : 1.0f;  // q0 role sign (q0 = thread bit)

    float m0 = g_m[2]  * (sgT * sZ45) + g_m[0]  * sX0  + g_m[1]  * (sgT * sZY0);
    float m1 = g_m[6]  * sZ1          + g_m[4]  * sEx1 + g_m[5]  * sEy1;
    float m2 = g_m[10] * sZ2          + g_m[8]  * sEx2 + g_m[9]  * sEy2;
    float m3 = g_m[14] * sZ3          + g_m[12] * sEx3 + g_m[13] * sEy3;
    float m4 = g_m[18] * sZ4          + g_m[16] * sX45 + g_m[17] * sY45;
    float m5 = g_m[22] * sZ45         + g_m[20] * sX50 + g_m[21] * sZYX;

    // reduce across the 2-thread group
    m0 += __shfl_xor_sync(0xffffffffu, m0, 1);
    m1 += __shfl_xor_sync(0xffffffffu, m1, 1);
    m2 += __shfl_xor_sync(0xffffffffu, m2, 1);
    m3 += __shfl_xor_sync(0xffffffffu, m3, 1);
    m4 += __shfl_xor_sync(0xffffffffu, m4, 1);
    m5 += __shfl_xor_sync(0xffffffffu, m5, 1);

    if (t == 0) {
        float4* o4 = reinterpret_cast<float4*>(out) + (long)st * 2;
        o4[0] = make_float4(m0, m1, m2, m3);
        o4[1] = make_float4(m4, m5, m0, m1);
    }
}

extern "C" void kernel_launch(void* const* d_in, const int* in_sizes, int n_in,
                              void* d_out, int out_size) {
    const float* x     = (const float*)d_in[0];
    const float* theta = (const float*)d_in[1];
    float* out = (float*)d_out;
    int Bn = in_sizes[0] / 24;

    prep_kernel<<<1, 32>>>(theta);
    long threads = 2L * Bn;
    int blocks = (int)((threads + 127) / 128);
    qsim_kernel<<<blocks, 128>>>(x, out, Bn);
}

// round 15
// speedup vs baseline: 1.2540x; 1.2540x over previous
#include <cuda_runtime.h>

// ---------------------------------------------------------------------------
// 6-qubit, 3-layer circuit, B=131072. TWO threads per state (t = q0), each
// holding 16 packed-f32x2 real + 16 imag regs (lane = q5; pack bits
// 3..0 = q1,q2,q3,q4).
//  * Layer-1 CNOT ring + its q0,q1 gates absorbed analytically into build.
//  * Layer-1 q2,q3,q4 gates absorbed into the build's TENSOR STAGES:
//      amp' = sum_{y3o} U3[y3,y3o] * CRm[y1][y2][y3o] * K4[y3o][y4]
//      CRm[y1][y2][y3o] = sum_{y2o} U2[y2,y2o] V[y1][y2o] u3[y2o^y3o]
//      K4[y3o][y4]      = sum_{y4o} U4[y4,y4o] u4[y4o^y3o] u5pack(y4o)
//    (U2 on 8-entry tensor, U4 on 4-entry table, U3 folded into K~.)
//  * Layer-1 q5 gate: local packed butterfly (lane).
//  * Layer 2: C01 = t-predicated SELs; C12/C23/C34 renames; C45+C50 folded
//    into the cross-thread q0-gate gather (partner xor 1); q1..q5 local.
//  * Layer 3: C01 SELs + C12/C23/C34 renames; C45, C50 and all six gates
//    absorbed into observables (Heisenberg).
// ---------------------------------------------------------------------------

typedef unsigned long long u64;
#define SGN2 0x8000000080000000ULL

__device__ __forceinline__ u64 pk2(float a, float b) {
    u64 r; asm("mov.b64 %0,{%1,%2};" : "=l"(r) : "f"(a), "f"(b)); return r;
}
__device__ __forceinline__ void upk2(u64 v, float& a, float& b) {
    asm("mov.b64 {%0,%1},%2;" : "=f"(a), "=f"(b) : "l"(v));
}
__device__ __forceinline__ u64 bc2(float a) { return pk2(a, a); }
__device__ __forceinline__ u64 f2mul(u64 a, u64 b) {
    u64 d; asm("mul.rn.f32x2 %0,%1,%2;" : "=l"(d) : "l"(a), "l"(b)); return d;
}
__device__ __forceinline__ u64 f2fma(u64 a, u64 b, u64 c) {
    u64 d; asm("fma.rn.f32x2 %0,%1,%2,%3;" : "=l"(d) : "l"(a), "l"(b), "l"(c)); return d;
}
__device__ __forceinline__ u64 f2add(u64 a, u64 b) {
    u64 d; asm("add.rn.f32x2 %0,%1,%2;" : "=l"(d) : "l"(a), "l"(b)); return d;
}
__device__ __forceinline__ u64 f2swap(u64 a) {
    u64 d;
    asm("{\n\t.reg .b32 x,y;\n\tmov.b64 {x,y},%1;\n\tmov.b64 %0,{y,x};\n\t}"
        : "=l"(d) : "l"(a));
    return d;
}

// g_u[40..45]: layer-1 q5 table.
// g_u[48..95]: layer-2 table: q0 at +0 [ar,ai,br,bi,-bi]; q1 at +8 and
//   q2..q4 at +16/+24/+32 [ar,ai,-ai,br,-br,bi,-bi]; q5 at +40.
__device__ u64 g_u[2 * 48];
// Layer-1 q0..q4 raw SU(2) coefficients: [q*4] = ar, ai, br, bi
__device__ float g_l1[20];
// Observable combine constants per qubit: [cx, cy, cz, pad]
__device__ float g_m[24];

__global__ void prep_kernel(const float* __restrict__ theta) {
    int t = threadIdx.x;
    if (t < 18) {
        int l = t / 6, q = t % 6;
        const float* th = theta + t * 3;
        float sx, cx, sy, cy, sz, cz;
        __sincosf(th[0] * 0.5f, &sx, &cx);
        __sincosf(th[1] * 0.5f, &sy, &cy);
        __sincosf(th[2] * 0.5f, &sz, &cz);
        float m00r =  cy * cx, m00i =  sy * sx;
        float m01r = -sy * cx, m01i = -cy * sx;
        float ar = cz * m00r + sz * m00i, ai = cz * m00i - sz * m00r;
        float br = cz * m01r + sz * m01i, bi = cz * m01i - sz * m01r;
        if (l == 0) {
            if (q <= 4) {
                g_l1[q * 4 + 0] = ar; g_l1[q * 4 + 1] = ai;
                g_l1[q * 4 + 2] = br; g_l1[q * 4 + 3] = bi;
            } else {
                u64* h = g_u + 40;
                h[0] = pk2(ar, ar);   h[1] = pk2(-ai, ai);
                h[2] = pk2(br, -br);  h[3] = pk2(-bi, -bi);
                h[4] = pk2(ai, -ai);  h[5] = pk2(bi, bi);
            }
        } else if (l == 1) {
            u64* g = g_u + 48;
            if (q == 0) {
                g[0] = bc2(ar); g[1] = bc2(ai); g[2] = bc2(br);
                g[3] = bc2(bi); g[4] = bc2(-bi);
            } else if (q < 5) {
                u64* h = g + 8 + (q - 1) * 8;
                h[0] = bc2(ar); h[1] = bc2(ai); h[2] = bc2(-ai);
                h[3] = bc2(br); h[4] = bc2(-br); h[5] = bc2(bi); h[6] = bc2(-bi);
            } else {
                u64* h = g + 40;
                h[0] = pk2(ar, ar);   h[1] = pk2(-ai, ai);
                h[2] = pk2(br, -br);  h[3] = pk2(-bi, -bi);
                h[4] = pk2(ai, -ai);  h[5] = pk2(bi, bi);
            }
        } else {
            // layer 3 observable n-vector. even q: U†ZU, odd q: U†XU
            float nx, ny, nz;
            if ((q & 1) == 0) {
                nz = (ar * ar + ai * ai) - (br * br + bi * bi);
                nx = 2.0f * (br * ar + bi * ai);
                ny = 2.0f * (br * ai - bi * ar);
            } else {
                nz = -2.0f * (ar * br - ai * bi);
                nx = ar * ar - ai * ai - br * br + bi * bi;
                ny = 2.0f * (ar * ai + br * bi);
            }
            if (q == 1 || q == 2 || q == 3) { nx *= 2.0f; ny *= 2.0f; }
            if (q == 4) { ny *= 2.0f; }
            g_m[q * 4 + 0] = nx;
            g_m[q * 4 + 1] = ny;
            g_m[q * 4 + 2] = nz;
        }
    }
}

// Local SU(2) on pack bit (MP = 8 -> q1, 4 -> q2, 2 -> q3, 1 -> q4).
template <int MP>
__device__ __forceinline__ void su2_loc(u64* R, u64* I, const u64* __restrict__ u) {
    u64 ar = u[0], ai = u[1], nai = u[2];
    u64 br = u[3], nbr = u[4], bi = u[5], nbi = u[6];
#pragma unroll
    for (int g = 0; g < 8; g++) {
        int p0 = (g & (MP - 1)) | ((g & ~(MP - 1)) << 1);
        int p1 = p0 | MP;
        u64 Ar = R[p0], Ai = I[p0], Br = R[p1], Bi = I[p1];
        R[p0] = f2fma(nbi, Bi, f2fma(br, Br, f2fma(nai, Ai, f2mul(ar, Ar))));
        I[p0] = f2fma(br, Bi, f2fma(bi, Br, f2fma(ai, Ar, f2mul(ar, Ai))));
        R[p1] = f2fma(ai, Bi, f2fma(ar, Br, f2fma(nbi, Ai, f2mul(nbr, Ar))));
        I[p1] = f2fma(nai, Br, f2fma(ar, Bi, f2fma(bi, Ar, f2mul(nbr, Ai))));
    }
}

// Local SU(2) on qubit 5 (lane), within-pack butterfly via half-swap.
__device__ __forceinline__ void su2_q5(u64* R, u64* I, const u64* __restrict__ u) {
    u64 aa = u[0], am = u[1], bp = u[2], nb2 = u[3], ap = u[4], bb = u[5];
#pragma unroll
    for (int p = 0; p < 16; p++) {
        u64 r = R[p], m = I[p];
        u64 sr = f2swap(r), sm = f2swap(m);
        R[p] = f2fma(nb2, sm, f2fma(bp, sr, f2fma(am, m, f2mul(aa, r))));
        I[p] = f2fma(bb, sr, f2fma(bp, sm, f2fma(ap, r, f2mul(aa, m))));
    }
}

__device__ __forceinline__ void swp(u64* A, int i, int j) {
    u64 t = A[i]; A[i] = A[j]; A[j] = t;
}

// CNOT(1,2),(2,3),(3,4) as register renames on the 16-pack array.
__device__ __forceinline__ void cnot_ring_mid(u64* R, u64* I) {
    swp(R, 8, 12); swp(R, 9, 13); swp(R, 10, 14); swp(R, 11, 15);
    swp(I, 8, 12); swp(I, 9, 13); swp(I, 10, 14); swp(I, 11, 15);
    swp(R, 4, 6); swp(R, 5, 7); swp(R, 12, 14); swp(R, 13, 15);
    swp(I, 4, 6); swp(I, 5, 7); swp(I, 12, 14); swp(I, 13, 15);
    swp(R, 2, 3); swp(R, 6, 7); swp(R, 10, 11); swp(R, 14, 15);
    swp(I, 2, 3); swp(I, 6, 7); swp(I, 10, 11); swp(I, 14, 15);
}

// CNOT(0,1): control = thread bit, target = pack bit3 (predicated SELs).
__device__ __forceinline__ void cnot01(u64* R, u64* I, bool c) {
#pragma unroll
    for (int p = 0; p < 8; p++) {
        u64 a = R[p], b = R[p + 8];
        R[p] = c ? b : a;  R[p + 8] = c ? a : b;
        a = I[p]; b = I[p + 8];
        I[p] = c ? b : a;  I[p + 8] = c ? a : b;
    }
}

__global__ __launch_bounds__(128, 5) void qsim_kernel(
    const float* __restrict__ x, float* __restrict__ out, int Bn)
{
    int gid = blockIdx.x * 128 + threadIdx.x;
    int st = gid >> 1;
    if (st >= Bn) return;
    int t = gid & 1;

    // --- encoding (1 sincos per qubit; double-angle for a/2 terms) ---
    const float4* x4 = reinterpret_cast<const float4*>(x) + (long)st * 6;
    float ur[6][2], ui[6][2];
#pragma unroll
    for (int q = 0; q < 6; q++) {
        float4 v = __ldg(&x4[q]);
        float a = (v.x + v.y + v.z + v.w) * 0.25f;
        a = fminf(6.0f, fmaxf(-6.0f, a)) * (3.14159265358979323846f / 6.0f);
        float s4, c4;
        __sincosf(a * 0.25f, &s4, &c4);
        float s2 = 2.0f * s4 * c4;
        float c2 = fmaf(-2.0f * s4, s4, 1.0f);
        ur[q][0] = c2 * c4;  ui[q][0] = -c2 * s4;
        ur[q][1] = s2 * s4;  ui[q][1] = -s2 * c4;
    }

    // --- build: U0 row t contracted; U1 expands pack bit3 (y1) ---
    float C0r, C0i, C1r, C1i;
    {
        float a0r = g_l1[0], a0i = g_l1[1], b0r = g_l1[2], b0i = g_l1[3];
        C0r = t ? -b0r : a0r;  C0i = t ?  b0i : a0i;
        C1r = t ?  a0r : b0r;  C1i = t ? -a0i : b0i;
    }
    float a1r = g_l1[4], a1i = g_l1[5], b1r = g_l1[6], b1i = g_l1[7];

    float Vr[2][2][2], Vi[2][2][2];  // [y1][y2o][y5]
    {
        float Tr[2][2], Ti[2][2];  // [c0][y5]
#pragma unroll
        for (int y5 = 0; y5 < 2; y5++) {
            Tr[0][y5] = C0r * ur[0][y5] - C0i * ui[0][y5];
            Ti[0][y5] = C0r * ui[0][y5] + C0i * ur[0][y5];
            Tr[1][y5] = C1r * ur[0][1 ^ y5] - C1i * ui[0][1 ^ y5];
            Ti[1][y5] = C1r * ui[0][1 ^ y5] + C1i * ur[0][1 ^ y5];
        }
        float Wr[2][2], Wi[2][2];  // [c1][y5]
#pragma unroll
        for (int c1 = 0; c1 < 2; c1++)
#pragma unroll
            for (int y5 = 0; y5 < 2; y5++) {
                int j = c1 ^ y5;
                Wr[c1][y5] = Tr[0][y5] * ur[1][j] - Ti[0][y5] * ui[1][j]
                           + Tr[1][y5] * ur[1][j ^ 1] - Ti[1][y5] * ui[1][j ^ 1];
                Wi[c1][y5] = Tr[0][y5] * ui[1][j] + Ti[0][y5] * ur[1][j]
                           + Tr[1][y5] * ui[1][j ^ 1] + Ti[1][y5] * ur[1][j ^ 1];
            }
        // P[y1][c1][y5] = U1[y1,c1] * W[c1][y5];  U1 = [[a1,b1],[-b1*,a1*]]
        float Pr[2][2][2], Pi2[2][2][2];
#pragma unroll
        for (int y5 = 0; y5 < 2; y5++) {
            Pr[0][0][y5]  = a1r * Wr[0][y5] - a1i * Wi[0][y5];
            Pi2[0][0][y5] = a1r * Wi[0][y5] + a1i * Wr[0][y5];
            Pr[0][1][y5]  = b1r * Wr[1][y5] - b1i * Wi[1][y5];
            Pi2[0][1][y5] = b1r * Wi[1][y5] + b1i * Wr[1][y5];
            Pr[1][0][y5]  = -b1r * Wr[0][y5] - b1i * Wi[0][y5];
            Pi2[1][0][y5] = -b1r * Wi[0][y5] + b1i * Wr[0][y5];
            Pr[1][1][y5]  = a1r * Wr[1][y5] + a1i * Wi[1][y5];
            Pi2[1][1][y5] = a1r * Wi[1][y5] - a1i * Wr[1][y5];
        }
#pragma unroll
        for (int y1 = 0; y1 < 2; y1++)
#pragma unroll
            for (int y2 = 0; y2 < 2; y2++)
#pragma unroll
                for (int y5 = 0; y5 < 2; y5++) {
                    Vr[y1][y2][y5] =
                        Pr[y1][0][y5] * ur[2][y2] - Pi2[y1][0][y5] * ui[2][y2]
                      + Pr[y1][1][y5] * ur[2][y2 ^ 1] - Pi2[y1][1][y5] * ui[2][y2 ^ 1];
                    Vi[y1][y2][y5] =
                        Pr[y1][0][y5] * ui[2][y2] + Pi2[y1][0][y5] * ur[2][y2]
                      + Pr[y1][1][y5] * ui[2][y2 ^ 1] + Pi2[y1][1][y5] * ur[2][y2 ^ 1];
                }
    }

    // --- K tables with layer-1 U4 and U3 folded in ---
    u64 TKR[2][2][2], TKI[2][2][2];   // K~[y3][y3o][y4]
    {
        float k45r[2][2], k45i[2][2];
#pragma unroll
        for (int m = 0; m < 2; m++)
#pragma unroll
            for (int n = 0; n < 2; n++) {
                k45r[m][n] = ur[4][m] * ur[5][n] - ui[4][m] * ui[5][n];
                k45i[m][n] = ur[4][m] * ui[5][n] + ui[4][m] * ur[5][n];
            }
        u64 A4r = bc2(g_l1[16]), A4i = bc2(g_l1[17]);
        u64 B4r = bc2(g_l1[18]), B4i = bc2(g_l1[19]);
        u64 A3r = bc2(g_l1[12]), A3i = bc2(g_l1[13]);
        u64 B3r = bc2(g_l1[14]), B3i = bc2(g_l1[15]);
#pragma unroll
        for (int y3o = 0; y3o < 2; y3o++) {
            int m0 = 0 ^ y3o, m1 = 1 ^ y3o;
            u64 r0 = pk2(k45r[m0][0], k45r[m0][1]);
            u64 i0 = pk2(k45i[m0][0], k45i[m0][1]);
            u64 r1 = pk2(k45r[m1][1], k45r[m1][0]);
            u64 i1 = pk2(k45i[m1][1], k45i[m1][0]);
            // K4[y3o][0] = a4*K[y3o][0] + b4*K[y3o][1]
            u64 K40R = f2fma(B4i ^ SGN2, i1, f2fma(B4r, r1,
                        f2fma(A4i ^ SGN2, i0, f2mul(A4r, r0))));
            u64 K40I = f2fma(B4i, r1, f2fma(B4r, i1,
                        f2fma(A4i, r0, f2mul(A4r, i0))));
            // K4[y3o][1] = -b4* * K[y3o][0] + a4* * K[y3o][1]
            u64 K41R = f2fma(A4i, i1, f2fma(A4r, r1,
                        f2fma(B4i ^ SGN2, i0, f2mul(B4r ^ SGN2, r0))));
            u64 K41I = f2fma(A4i ^ SGN2, r1, f2fma(A4r, i1,
                        f2fma(B4i, r0, f2mul(B4r ^ SGN2, i0))));
            // K~[0][y3o] = U3[0,y3o]*K4 ; K~[1][y3o] = U3[1,y3o]*K4
            u64 cr0, ci0, cr1, ci1;
            if (y3o == 0) { cr0 = A3r; ci0 = A3i; cr1 = B3r ^ SGN2; ci1 = B3i; }
            else          { cr0 = B3r; ci0 = B3i; cr1 = A3r; ci1 = A3i ^ SGN2; }
            TKR[0][y3o][0] = f2fma(ci0 ^ SGN2, K40I, f2mul(cr0, K40R));
            TKI[0][y3o][0] = f2fma(ci0, K40R, f2mul(cr0, K40I));
            TKR[0][y3o][1] = f2fma(ci0 ^ SGN2, K41I, f2mul(cr0, K41R));
            TKI[0][y3o][1] = f2fma(ci0, K41R, f2mul(cr0, K41I));
            TKR[1][y3o][0] = f2fma(ci1 ^ SGN2, K40I, f2mul(cr1, K40R));
            TKI[1][y3o][0] = f2fma(ci1, K40R, f2mul(cr1, K40I));
            TKR[1][y3o][1] = f2fma(ci1 ^ SGN2, K41I, f2mul(cr1, K41R));
            TKI[1][y3o][1] = f2fma(ci1, K41R, f2mul(cr1, K41I));
        }
    }
    // Note: K[y3o][y4] lane pair = (k45[m][y4], k45[m][y4^1]) with m=y4^y3o.
    // For y4=1: m = 1^y3o, lanes = (k45[m][1], k45[m][0]) -> r1/i1 above.

    // --- CRm (with U2 folded) and expansion via K~ ---
    u64 R[16], I[16];
    {
        u64 w3r[2], w3i[2], n3i[2];
        w3r[0] = bc2(ur[3][0]); w3i[0] = bc2(ui[3][0]); n3i[0] = w3i[0] ^ SGN2;
        w3r[1] = bc2(ur[3][1]); w3i[1] = bc2(ui[3][1]); n3i[1] = w3i[1] ^ SGN2;
        u64 A2r = bc2(g_l1[8]),  A2i = bc2(g_l1[9]);
        u64 B2r = bc2(g_l1[10]), B2i = bc2(g_l1[11]);
#pragma unroll
        for (int y1 = 0; y1 < 2; y1++) {
            // CRm0[y2o][y3o] = V[y1][y2o] * u3[y2o^y3o]
            u64 c0R[2], c0I[2], c1R[2], c1I[2];
            {
                u64 BR = pk2(Vr[y1][0][0], Vr[y1][0][1]);
                u64 BI = pk2(Vi[y1][0][0], Vi[y1][0][1]);
#pragma unroll
                for (int y3o = 0; y3o < 2; y3o++) {
                    int m = y3o;
                    c0R[y3o] = f2fma(n3i[m], BI, f2mul(w3r[m], BR));
                    c0I[y3o] = f2fma(w3i[m], BR, f2mul(w3r[m], BI));
                }
                BR = pk2(Vr[y1][1][0], Vr[y1][1][1]);
                BI = pk2(Vi[y1][1][0], Vi[y1][1][1]);
#pragma unroll
                for (int y3o = 0; y3o < 2; y3o++) {
                    int m = 1 ^ y3o;
                    c1R[y3o] = f2fma(n3i[m], BI, f2mul(w3r[m], BR));
                    c1I[y3o] = f2fma(w3i[m], BR, f2mul(w3r[m], BI));
                }
            }
            // U2 butterfly over y2o -> D[y2][y3o]
            u64 DR[2][2], DI[2][2];
#pragma unroll
            for (int y3o = 0; y3o < 2; y3o++) {
                u64 r0 = c0R[y3o], i0 = c0I[y3o];
                u64 r1 = c1R[y3o], i1 = c1I[y3o];
                DR[0][y3o] = f2fma(B2i ^ SGN2, i1, f2fma(B2r, r1,
                              f2fma(A2i ^ SGN2, i0, f2mul(A2r, r0))));
                DI[0][y3o] = f2fma(B2i, r1, f2fma(B2r, i1,
                              f2fma(A2i, r0, f2mul(A2r, i0))));
                DR[1][y3o] = f2fma(A2i, i1, f2fma(A2r, r1,
                              f2fma(B2i ^ SGN2, i0, f2mul(B2r ^ SGN2, r0))));
                DI[1][y3o] = f2fma(A2i ^ SGN2, r1, f2fma(A2r, i1,
                              f2fma(B2i, r0, f2mul(B2r ^ SGN2, i0))));
            }
            // expansion: amp(p) = sum_{y3o} D[y2][y3o] * K~[y3][y3o][y4]
#pragma unroll
            for (int y2 = 0; y2 < 2; y2++) {
                u64 xr0 = DR[y2][0], xi0 = DI[y2][0];
                u64 xr1 = DR[y2][1], xi1 = DI[y2][1];
                u64 nxi0 = xi0 ^ SGN2, nxi1 = xi1 ^ SGN2;
#pragma unroll
                for (int y3 = 0; y3 < 2; y3++)
#pragma unroll
                    for (int y4 = 0; y4 < 2; y4++) {
                        int p = (y1 << 3) | (y2 << 2) | (y3 << 1) | y4;
                        R[p] = f2fma(nxi1, TKI[y3][1][y4], f2fma(xr1, TKR[y3][1][y4],
                                f2fma(nxi0, TKI[y3][0][y4], f2mul(xr0, TKR[y3][0][y4]))));
                        I[p] = f2fma(xi1, TKR[y3][1][y4], f2fma(xr1, TKI[y3][1][y4],
                                f2fma(xi0, TKR[y3][0][y4], f2mul(xr0, TKI[y3][0][y4]))));
                    }
            }
        }
    }

    // --- layer-1 q5 gate (lane) ---
    su2_q5(R, I, g_u + 40);

    // --- layer 2 (full) ---
    {
        const u64* cf = g_u + 48;
        cnot01(R, I, t != 0);
        cnot_ring_mid(R, I);

        // q0 gate (cross-thread, partner xor 1), C45 + C50 folded into gather.
        {
            u64 smask = t ? SGN2 : 0ULL;
            u64 car  = cf[0];
            u64 cai  = cf[1] ^ smask;
            u64 ncai = cai ^ SGN2;
            u64 cbr  = cf[2] ^ smask;
            u64 cbi  = cf[3];
            u64 ncbi = cf[4];
#pragma unroll
            for (int p = 0; p < 16; p++) {
                u64 LR = R[p], LI = I[p];
                u64 MR = __shfl_xor_sync(0xffffffffu, LR, 1);
                u64 MI = __shfl_xor_sync(0xffffffffu, LI, 1);
                float lr0, lr1, li0, li1, mr0, mr1, mi0, mi1;
                upk2(LR, lr0, lr1); upk2(LI, li0, li1);
                upk2(MR, mr0, mr1); upk2(MI, mi0, mi1);
                u64 AR, AI, BR, BI;
                if ((p & 1) == 0) {  // q4=0: C45 identity, C50 hi-lane cross
                    AR = pk2(lr0, mr1); AI = pk2(li0, mi1);
                    BR = pk2(mr0, lr1); BI = pk2(mi0, li1);
                } else {             // q4=1: C45 lane-swap then C50
                    AR = pk2(lr1, mr0); AI = pk2(li1, mi0);
                    BR = pk2(mr1, lr0); BI = pk2(mi1, li0);
                }
                R[p] = f2fma(ncbi, BI, f2fma(cbr, BR, f2fma(ncai, AI, f2mul(car, AR))));
                I[p] = f2fma(cbi, BR, f2fma(cbr, BI, f2fma(cai, AR, f2mul(car, AI))));
            }
        }

        su2_loc<8>(R, I, cf + 8);   // q1 (bit3)
        su2_loc<4>(R, I, cf + 16);  // q2 (bit2)
        su2_loc<2>(R, I, cf + 24);  // q3 (bit1)
        su2_loc<1>(R, I, cf + 32);  // q4 (bit0)
        su2_q5(R, I, cf + 40);      // q5 (lane)
    }

    // --- layer-3 prefix: C01 SEL + C12/C23/C34 renames; rest absorbed ---
    cnot01(R, I, t != 0);
    cnot_ring_mid(R, I);

    // --- measurements (R13 structure: merged loops for ILP) ---
    float sZ1, sZ2, sZ3, sZ4, sZ45;
    float sEx1, sEy1, sEx2, sEy2, sEx3, sEy3, sX45, sY45;
    {
        u64 az1 = 0, az2 = 0, az3 = 0, az4 = 0;
        u64 ex1 = 0, ey1 = 0, ex2 = 0, ey2 = 0, ex3 = 0, ey3 = 0;
        u64 x45 = 0, y45 = 0;
#pragma unroll
        for (int p = 0; p < 16; p++) {
            u64 pr = f2fma(I[p], I[p], f2mul(R[p], R[p]));
            az1 = f2add(az1, (p & 8) ? (pr ^ SGN2) : pr);
            az2 = f2add(az2, (p & 4) ? (pr ^ SGN2) : pr);
            az3 = f2add(az3, (p & 2) ? (pr ^ SGN2) : pr);
            az4 = f2add(az4, (p & 1) ? (pr ^ SGN2) : pr);
            if (!(p & 8)) {
                ex1 = f2fma(R[p], R[p | 8], f2fma(I[p], I[p | 8], ex1));
                ey1 = f2fma(R[p], I[p | 8], f2fma(I[p] ^ SGN2, R[p | 8], ey1));
            }
            if (!(p & 4)) {
                ex2 = f2fma(R[p], R[p | 4], f2fma(I[p], I[p | 4], ex2));
                ey2 = f2fma(R[p], I[p | 4], f2fma(I[p] ^ SGN2, R[p | 4], ey2));
            }
            if (!(p & 2)) {
                ex3 = f2fma(R[p], R[p | 2], f2fma(I[p], I[p | 2], ex3));
                ey3 = f2fma(R[p], I[p | 2], f2fma(I[p] ^ SGN2, R[p | 2], ey3));
            }
            x45 = f2fma(R[p], f2swap(R[p ^ 1]), f2fma(I[p], f2swap(I[p ^ 1]), x45));
            if (!(p & 1)) {
                y45 = f2fma(R[p], f2swap(I[p | 1]),
                            f2fma(I[p] ^ SGN2, f2swap(R[p | 1]), y45));
            }
        }
        float lo, hi;
        upk2(az1, lo, hi); sZ1  = lo + hi;
        upk2(az2, lo, hi); sZ2  = lo + hi;
        upk2(az3, lo, hi); sZ3  = lo + hi;
        upk2(az4, lo, hi); sZ4  = lo + hi; sZ45 = lo - hi;
        upk2(ex1, lo, hi); sEx1 = lo + hi;
        upk2(ey1, lo, hi); sEy1 = lo + hi;
        upk2(ex2, lo, hi); sEx2 = lo + hi;
        upk2(ey2, lo, hi); sEy2 = lo + hi;
        upk2(ex3, lo, hi); sEx3 = lo + hi;
        upk2(ey3, lo, hi); sEy3 = lo + hi;
        upk2(x45, lo, hi); sX45 = lo + hi;
        upk2(y45, lo, hi); sY45 = lo + hi;
    }

    // cross-thread q0 observables (partner = lane xor 1)
    float sX0, sZY0, sX50, sZYX;
    {
        u64 ax0 = 0, zy0 = 0, x50 = 0, zyx = 0;
#pragma unroll
        for (int p = 0; p < 16; p++) {
            u64 PR = __shfl_xor_sync(0xffffffffu, R[p], 1);
            u64 PI = __shfl_xor_sync(0xffffffffu, I[p], 1);
            ax0 = f2fma(R[p], PR, f2fma(I[p], PI, ax0));
            {
                u64 v = f2fma(R[p], PI, f2mul(I[p] ^ SGN2, PR));
                zy0 = f2add(zy0, (p & 1) ? (v ^ SGN2) : v);
            }
            x50 = f2fma(R[p], f2swap(PR), f2fma(I[p], f2swap(PI), x50));
            {
                u64 v = f2fma(R[p], f2swap(PI), f2mul(I[p] ^ SGN2, f2swap(PR)));
                zyx = f2add(zyx, (p & 1) ? (v ^ SGN2) : v);
            }
        }
        float lo, hi;
        upk2(ax0, lo, hi); sX0  = lo + hi;
        upk2(zy0, lo, hi); sZY0 = lo - hi;
        upk2(x50, lo, hi); sX50 = lo + hi;
        upk2(zyx, lo, hi); sZYX = lo - hi;
    }

    float sgT = t ? -1.0f : 1.0f;  // q0 role sign (q0 = thread bit)

    float m0 = g_m[2]  * (sgT * sZ45) + g_m[0]  * sX0  + g_m[1]  * (sgT * sZY0);
    float m1 = g_m[6]  * sZ1          + g_m[4]  * sEx1 + g_m[5]  * sEy1;
    float m2 = g_m[10] * sZ2          + g_m[8]  * sEx2 + g_m[9]  * sEy2;
    float m3 = g_m[14] * sZ3          + g_m[12] * sEx3 + g_m[13] * sEy3;
    float m4 = g_m[18] * sZ4          + g_m[16] * sX45 + g_m[17] * sY45;
    float m5 = g_m[22] * sZ45         + g_m[20] * sX50 + g_m[21] * sZYX;

    // reduce across the 2-thread group
    m0 += __shfl_xor_sync(0xffffffffu, m0, 1);
    m1 += __shfl_xor_sync(0xffffffffu, m1, 1);
    m2 += __shfl_xor_sync(0xffffffffu, m2, 1);
    m3 += __shfl_xor_sync(0xffffffffu, m3, 1);
    m4 += __shfl_xor_sync(0xffffffffu, m4, 1);
    m5 += __shfl_xor_sync(0xffffffffu, m5, 1);

    if (t == 0) {
        float4* o4 = reinterpret_cast<float4*>(out) + (long)st * 2;
        o4[0] = make_float4(m0, m1, m2, m3);
        o4[1] = make_float4(m4, m5, m0, m1);
    }
}

extern "C" void kernel_launch(void* const* d_in, const int* in_sizes, int n_in,
                              void* d_out, int out_size) {
    const float* x     = (const float*)d_in[0];
    const float* theta = (const float*)d_in[1];
    float* out = (float*)d_out;
    int Bn = in_sizes[0] / 24;

    prep_kernel<<<1, 32>>>(theta);
    long threads = 2L * Bn;
    int blocks = (int)((threads + 127) / 128);
    qsim_kernel<<<blocks, 128>>>(x, out, Bn);
}

// round 16
// speedup vs baseline: 1.2776x; 1.0188x over previous
#include <cuda_runtime.h>

// ---------------------------------------------------------------------------
// 6-qubit, 3-layer circuit, B=131072. TWO threads per state (t = q0), each
// holding 16 packed-f32x2 real + 16 imag regs (lane = q5; pack bits
// 3..0 = q1,q2,q3,q4).
//  * Layer-1 CNOT ring + its q0,q1 gates absorbed analytically into build.
//  * Layer-1 q2,q3,q4 gates absorbed into the build's tensor stages.
//  * Build's scalar head (T/W/P/V) is lane-packed over y5 (f32x2 throughout).
//  * Layer-1 q5 gate: local packed butterfly (lane).
//  * Layer 2: C01 = t-predicated SELs; C12/C23/C34 renames; C45+C50 folded
//    into the cross-thread q0-gate gather (partner xor 1); q1..q5 local.
//  * Layer 3: C01 SELs + C12/C23/C34 renames; C45, C50 and all six gates
//    absorbed into observables (Heisenberg). X4X5 sum halved (even packs,
//    2x folded into g_m).
// ---------------------------------------------------------------------------

typedef unsigned long long u64;
#define SGN2 0x8000000080000000ULL

__device__ __forceinline__ u64 pk2(float a, float b) {
    u64 r; asm("mov.b64 %0,{%1,%2};" : "=l"(r) : "f"(a), "f"(b)); return r;
}
__device__ __forceinline__ void upk2(u64 v, float& a, float& b) {
    asm("mov.b64 {%0,%1},%2;" : "=f"(a), "=f"(b) : "l"(v));
}
__device__ __forceinline__ u64 bc2(float a) { return pk2(a, a); }
__device__ __forceinline__ u64 f2mul(u64 a, u64 b) {
    u64 d; asm("mul.rn.f32x2 %0,%1,%2;" : "=l"(d) : "l"(a), "l"(b)); return d;
}
__device__ __forceinline__ u64 f2fma(u64 a, u64 b, u64 c) {
    u64 d; asm("fma.rn.f32x2 %0,%1,%2,%3;" : "=l"(d) : "l"(a), "l"(b), "l"(c)); return d;
}
__device__ __forceinline__ u64 f2add(u64 a, u64 b) {
    u64 d; asm("add.rn.f32x2 %0,%1,%2;" : "=l"(d) : "l"(a), "l"(b)); return d;
}
__device__ __forceinline__ u64 f2swap(u64 a) {
    u64 d;
    asm("{\n\t.reg .b32 x,y;\n\tmov.b64 {x,y},%1;\n\tmov.b64 %0,{y,x};\n\t}"
        : "=l"(d) : "l"(a));
    return d;
}

// g_u[40..45]: layer-1 q5 table.
// g_u[48..95]: layer-2 table: q0 at +0 [ar,ai,br,bi,-bi]; q1..q4 at
//   +8/+16/+24/+32 [ar,ai,-ai,br,-br,bi,-bi]; q5 at +40.
__device__ u64 g_u[2 * 48];
// Layer-1 q0..q4 raw SU(2) coefficients: [q*4] = ar, ai, br, bi
__device__ float g_l1[20];
// Observable combine constants per qubit: [cx, cy, cz, pad]
__device__ float g_m[24];

__global__ void prep_kernel(const float* __restrict__ theta) {
    int t = threadIdx.x;
    if (t < 18) {
        int l = t / 6, q = t % 6;
        const float* th = theta + t * 3;
        float sx, cx, sy, cy, sz, cz;
        __sincosf(th[0] * 0.5f, &sx, &cx);
        __sincosf(th[1] * 0.5f, &sy, &cy);
        __sincosf(th[2] * 0.5f, &sz, &cz);
        float m00r =  cy * cx, m00i =  sy * sx;
        float m01r = -sy * cx, m01i = -cy * sx;
        float ar = cz * m00r + sz * m00i, ai = cz * m00i - sz * m00r;
        float br = cz * m01r + sz * m01i, bi = cz * m01i - sz * m01r;
        if (l == 0) {
            if (q <= 4) {
                g_l1[q * 4 + 0] = ar; g_l1[q * 4 + 1] = ai;
                g_l1[q * 4 + 2] = br; g_l1[q * 4 + 3] = bi;
            } else {
                u64* h = g_u + 40;
                h[0] = pk2(ar, ar);   h[1] = pk2(-ai, ai);
                h[2] = pk2(br, -br);  h[3] = pk2(-bi, -bi);
                h[4] = pk2(ai, -ai);  h[5] = pk2(bi, bi);
            }
        } else if (l == 1) {
            u64* g = g_u + 48;
            if (q == 0) {
                g[0] = bc2(ar); g[1] = bc2(ai); g[2] = bc2(br);
                g[3] = bc2(bi); g[4] = bc2(-bi);
            } else if (q < 5) {
                u64* h = g + 8 + (q - 1) * 8;
                h[0] = bc2(ar); h[1] = bc2(ai); h[2] = bc2(-ai);
                h[3] = bc2(br); h[4] = bc2(-br); h[5] = bc2(bi); h[6] = bc2(-bi);
            } else {
                u64* h = g + 40;
                h[0] = pk2(ar, ar);   h[1] = pk2(-ai, ai);
                h[2] = pk2(br, -br);  h[3] = pk2(-bi, -bi);
                h[4] = pk2(ai, -ai);  h[5] = pk2(bi, bi);
            }
        } else {
            // layer 3 observable n-vector. even q: U†ZU, odd q: U†XU
            float nx, ny, nz;
            if ((q & 1) == 0) {
                nz = (ar * ar + ai * ai) - (br * br + bi * bi);
                nx = 2.0f * (br * ar + bi * ai);
                ny = 2.0f * (br * ai - bi * ar);
            } else {
                nz = -2.0f * (ar * br - ai * bi);
                nx = ar * ar - ai * ai - br * br + bi * bi;
                ny = 2.0f * (ar * ai + br * bi);
            }
            if (q == 1 || q == 2 || q == 3) { nx *= 2.0f; ny *= 2.0f; }
            if (q == 4) { nx *= 2.0f; ny *= 2.0f; }  // X45 sum now single-sided
            g_m[q * 4 + 0] = nx;
            g_m[q * 4 + 1] = ny;
            g_m[q * 4 + 2] = nz;
        }
    }
}

// Local SU(2) on pack bit (MP = 8 -> q1, 4 -> q2, 2 -> q3, 1 -> q4).
template <int MP>
__device__ __forceinline__ void su2_loc(u64* R, u64* I, const u64* __restrict__ u) {
    u64 ar = u[0], ai = u[1], nai = u[2];
    u64 br = u[3], nbr = u[4], bi = u[5], nbi = u[6];
#pragma unroll
    for (int g = 0; g < 8; g++) {
        int p0 = (g & (MP - 1)) | ((g & ~(MP - 1)) << 1);
        int p1 = p0 | MP;
        u64 Ar = R[p0], Ai = I[p0], Br = R[p1], Bi = I[p1];
        R[p0] = f2fma(nbi, Bi, f2fma(br, Br, f2fma(nai, Ai, f2mul(ar, Ar))));
        I[p0] = f2fma(br, Bi, f2fma(bi, Br, f2fma(ai, Ar, f2mul(ar, Ai))));
        R[p1] = f2fma(ai, Bi, f2fma(ar, Br, f2fma(nbi, Ai, f2mul(nbr, Ar))));
        I[p1] = f2fma(nai, Br, f2fma(ar, Bi, f2fma(bi, Ar, f2mul(nbr, Ai))));
    }
}

// Local SU(2) on qubit 5 (lane), within-pack butterfly via half-swap.
__device__ __forceinline__ void su2_q5(u64* R, u64* I, const u64* __restrict__ u) {
    u64 aa = u[0], am = u[1], bp = u[2], nb2 = u[3], ap = u[4], bb = u[5];
#pragma unroll
    for (int p = 0; p < 16; p++) {
        u64 r = R[p], m = I[p];
        u64 sr = f2swap(r), sm = f2swap(m);
        R[p] = f2fma(nb2, sm, f2fma(bp, sr, f2fma(am, m, f2mul(aa, r))));
        I[p] = f2fma(bb, sr, f2fma(bp, sm, f2fma(ap, r, f2mul(aa, m))));
    }
}

__device__ __forceinline__ void swp(u64* A, int i, int j) {
    u64 t = A[i]; A[i] = A[j]; A[j] = t;
}

// CNOT(1,2),(2,3),(3,4) as register renames on the 16-pack array.
__device__ __forceinline__ void cnot_ring_mid(u64* R, u64* I) {
    swp(R, 8, 12); swp(R, 9, 13); swp(R, 10, 14); swp(R, 11, 15);
    swp(I, 8, 12); swp(I, 9, 13); swp(I, 10, 14); swp(I, 11, 15);
    swp(R, 4, 6); swp(R, 5, 7); swp(R, 12, 14); swp(R, 13, 15);
    swp(I, 4, 6); swp(I, 5, 7); swp(I, 12, 14); swp(I, 13, 15);
    swp(R, 2, 3); swp(R, 6, 7); swp(R, 10, 11); swp(R, 14, 15);
    swp(I, 2, 3); swp(I, 6, 7); swp(I, 10, 11); swp(I, 14, 15);
}

// CNOT(0,1): control = thread bit, target = pack bit3 (predicated SELs).
__device__ __forceinline__ void cnot01(u64* R, u64* I, bool c) {
#pragma unroll
    for (int p = 0; p < 8; p++) {
        u64 a = R[p], b = R[p + 8];
        R[p] = c ? b : a;  R[p + 8] = c ? a : b;
        a = I[p]; b = I[p + 8];
        I[p] = c ? b : a;  I[p + 8] = c ? a : b;
    }
}

__global__ __launch_bounds__(128, 5) void qsim_kernel(
    const float* __restrict__ x, float* __restrict__ out, int Bn)
{
    int gid = blockIdx.x * 128 + threadIdx.x;
    int st = gid >> 1;
    if (st >= Bn) return;
    int t = gid & 1;

    // --- encoding (1 sincos per qubit; double-angle for a/2 terms) ---
    const float4* x4 = reinterpret_cast<const float4*>(x) + (long)st * 6;
    float ur[6][2], ui[6][2];
#pragma unroll
    for (int q = 0; q < 6; q++) {
        float4 v = __ldg(&x4[q]);
        float a = (v.x + v.y + v.z + v.w) * 0.25f;
        a = fminf(6.0f, fmaxf(-6.0f, a)) * (3.14159265358979323846f / 6.0f);
        float s4, c4;
        __sincosf(a * 0.25f, &s4, &c4);
        float s2 = 2.0f * s4 * c4;
        float c2 = fmaf(-2.0f * s4, s4, 1.0f);
        ur[q][0] = c2 * c4;  ui[q][0] = -c2 * s4;
        ur[q][1] = s2 * s4;  ui[q][1] = -s2 * c4;
    }

    // --- build head, lane-packed over y5: T -> W -> P -> V ---
    u64 VR[2][2], VI[2][2];  // [y1][y2o], lane = y5
    {
        float C0r, C0i, C1r, C1i;
        {
            float a0r = g_l1[0], a0i = g_l1[1], b0r = g_l1[2], b0i = g_l1[3];
            C0r = t ? -b0r : a0r;  C0i = t ?  b0i : a0i;
            C1r = t ?  a0r : b0r;  C1i = t ? -a0i : b0i;
        }
        u64 U0R = pk2(ur[0][0], ur[0][1]), U0I = pk2(ui[0][0], ui[0][1]);
        u64 U1R = pk2(ur[1][0], ur[1][1]), U1I = pk2(ui[1][0], ui[1][1]);
        u64 sU0R = f2swap(U0R), sU0I = f2swap(U0I);
        u64 sU1R = f2swap(U1R), sU1I = f2swap(U1I);
        u64 cC0r = bc2(C0r), cC0i = bc2(C0i), nC0i = cC0i ^ SGN2;
        u64 cC1r = bc2(C1r), cC1i = bc2(C1i), nC1i = cC1i ^ SGN2;
        // T[c0] = C_{c0} * u0-row
        u64 T0R = f2fma(nC0i, U0I, f2mul(cC0r, U0R));
        u64 T0I = f2fma(cC0i, U0R, f2mul(cC0r, U0I));
        u64 T1R = f2fma(nC1i, sU0I, f2mul(cC1r, sU0R));
        u64 T1I = f2fma(cC1i, sU0R, f2mul(cC1r, sU0I));
        u64 nT0I = T0I ^ SGN2, nT1I = T1I ^ SGN2;
        // W[c1] = T0*u1[c1^y5] + T1*u1[c1^1^y5]
        u64 W0R = f2fma(nT1I, sU1I, f2fma(T1R, sU1R, f2fma(nT0I, U1I, f2mul(T0R, U1R))));
        u64 W0I = f2fma(T1I, sU1R, f2fma(T1R, sU1I, f2fma(T0I, U1R, f2mul(T0R, U1I))));
        u64 W1R = f2fma(nT1I, U1I, f2fma(T1R, U1R, f2fma(nT0I, sU1I, f2mul(T0R, sU1R))));
        u64 W1I = f2fma(T1I, U1R, f2fma(T1R, U1I, f2fma(T0I, sU1R, f2mul(T0R, sU1I))));
        // P[y1][c1] = U1gate[y1,c1] * W[c1];  U1gate = [[a1,b1],[-b1*,a1*]]
        u64 cA1r = bc2(g_l1[4]), cA1i = bc2(g_l1[5]), nA1i = cA1i ^ SGN2;
        u64 cB1r = bc2(g_l1[6]), cB1i = bc2(g_l1[7]), nB1i = cB1i ^ SGN2;
        u64 nB1r = cB1r ^ SGN2;
        u64 P00R = f2fma(nA1i, W0I, f2mul(cA1r, W0R));
        u64 P00I = f2fma(cA1i, W0R, f2mul(cA1r, W0I));
        u64 P01R = f2fma(nB1i, W1I, f2mul(cB1r, W1R));
        u64 P01I = f2fma(cB1i, W1R, f2mul(cB1r, W1I));
        u64 P10R = f2fma(nB1i, W0I, f2mul(nB1r, W0R));
        u64 P10I = f2fma(cB1i, W0R, f2mul(nB1r, W0I));
        u64 P11R = f2fma(cA1i, W1I, f2mul(cA1r, W1R));
        u64 P11I = f2fma(nA1i, W1R, f2mul(cA1r, W1I));
        // V[y1][y2o] = P[y1][0]*u2[y2o] + P[y1][1]*u2[y2o^1]
        u64 u2r0 = bc2(ur[2][0]), u2r1 = bc2(ur[2][1]);
        u64 u2i0 = bc2(ui[2][0]), u2i1 = bc2(ui[2][1]);
        u64 n2i0 = u2i0 ^ SGN2, n2i1 = u2i1 ^ SGN2;
        VR[0][0] = f2fma(n2i1, P01I, f2fma(u2r1, P01R, f2fma(n2i0, P00I, f2mul(u2r0, P00R))));
        VI[0][0] = f2fma(u2i1, P01R, f2fma(u2r1, P01I, f2fma(u2i0, P00R, f2mul(u2r0, P00I))));
        VR[0][1] = f2fma(n2i0, P01I, f2fma(u2r0, P01R, f2fma(n2i1, P00I, f2mul(u2r1, P00R))));
        VI[0][1] = f2fma(u2i0, P01R, f2fma(u2r0, P01I, f2fma(u2i1, P00R, f2mul(u2r1, P00I))));
        VR[1][0] = f2fma(n2i1, P11I, f2fma(u2r1, P11R, f2fma(n2i0, P10I, f2mul(u2r0, P10R))));
        VI[1][0] = f2fma(u2i1, P11R, f2fma(u2r1, P11I, f2fma(u2i0, P10R, f2mul(u2r0, P10I))));
        VR[1][1] = f2fma(n2i0, P11I, f2fma(u2r0, P11R, f2fma(n2i1, P10I, f2mul(u2r1, P10R))));
        VI[1][1] = f2fma(u2i0, P11R, f2fma(u2r0, P11I, f2fma(u2i1, P10R, f2mul(u2r1, P10I))));
    }

    // --- K tables with layer-1 U4 and U3 folded in ---
    u64 TKR[2][2][2], TKI[2][2][2];   // K~[y3][y3o][y4]
    {
        float k45r[2][2], k45i[2][2];
#pragma unroll
        for (int m = 0; m < 2; m++)
#pragma unroll
            for (int n = 0; n < 2; n++) {
                k45r[m][n] = ur[4][m] * ur[5][n] - ui[4][m] * ui[5][n];
                k45i[m][n] = ur[4][m] * ui[5][n] + ui[4][m] * ur[5][n];
            }
        u64 A4r = bc2(g_l1[16]), A4i = bc2(g_l1[17]);
        u64 B4r = bc2(g_l1[18]), B4i = bc2(g_l1[19]);
        u64 A3r = bc2(g_l1[12]), A3i = bc2(g_l1[13]);
        u64 B3r = bc2(g_l1[14]), B3i = bc2(g_l1[15]);
#pragma unroll
        for (int y3o = 0; y3o < 2; y3o++) {
            int m0 = 0 ^ y3o, m1 = 1 ^ y3o;
            u64 r0 = pk2(k45r[m0][0], k45r[m0][1]);
            u64 i0 = pk2(k45i[m0][0], k45i[m0][1]);
            u64 r1 = pk2(k45r[m1][1], k45r[m1][0]);
            u64 i1 = pk2(k45i[m1][1], k45i[m1][0]);
            u64 K40R = f2fma(B4i ^ SGN2, i1, f2fma(B4r, r1,
                        f2fma(A4i ^ SGN2, i0, f2mul(A4r, r0))));
            u64 K40I = f2fma(B4i, r1, f2fma(B4r, i1,
                        f2fma(A4i, r0, f2mul(A4r, i0))));
            u64 K41R = f2fma(A4i, i1, f2fma(A4r, r1,
                        f2fma(B4i ^ SGN2, i0, f2mul(B4r ^ SGN2, r0))));
            u64 K41I = f2fma(A4i ^ SGN2, r1, f2fma(A4r, i1,
                        f2fma(B4i, r0, f2mul(B4r ^ SGN2, i0))));
            u64 cr0, ci0, cr1, ci1;
            if (y3o == 0) { cr0 = A3r; ci0 = A3i; cr1 = B3r ^ SGN2; ci1 = B3i; }
            else          { cr0 = B3r; ci0 = B3i; cr1 = A3r; ci1 = A3i ^ SGN2; }
            TKR[0][y3o][0] = f2fma(ci0 ^ SGN2, K40I, f2mul(cr0, K40R));
            TKI[0][y3o][0] = f2fma(ci0, K40R, f2mul(cr0, K40I));
            TKR[0][y3o][1] = f2fma(ci0 ^ SGN2, K41I, f2mul(cr0, K41R));
            TKI[0][y3o][1] = f2fma(ci0, K41R, f2mul(cr0, K41I));
            TKR[1][y3o][0] = f2fma(ci1 ^ SGN2, K40I, f2mul(cr1, K40R));
            TKI[1][y3o][0] = f2fma(ci1, K40R, f2mul(cr1, K40I));
            TKR[1][y3o][1] = f2fma(ci1 ^ SGN2, K41I, f2mul(cr1, K41R));
            TKI[1][y3o][1] = f2fma(ci1, K41R, f2mul(cr1, K41I));
        }
    }

    // --- CRm (with U2 folded) and expansion via K~ ---
    u64 R[16], I[16];
    {
        u64 w3r[2], w3i[2], n3i[2];
        w3r[0] = bc2(ur[3][0]); w3i[0] = bc2(ui[3][0]); n3i[0] = w3i[0] ^ SGN2;
        w3r[1] = bc2(ur[3][1]); w3i[1] = bc2(ui[3][1]); n3i[1] = w3i[1] ^ SGN2;
        u64 A2r = bc2(g_l1[8]),  A2i = bc2(g_l1[9]);
        u64 B2r = bc2(g_l1[10]), B2i = bc2(g_l1[11]);
#pragma unroll
        for (int y1 = 0; y1 < 2; y1++) {
            u64 c0R[2], c0I[2], c1R[2], c1I[2];
            {
                u64 BR = VR[y1][0], BI = VI[y1][0];
#pragma unroll
                for (int y3o = 0; y3o < 2; y3o++) {
                    int m = y3o;
                    c0R[y3o] = f2fma(n3i[m], BI, f2mul(w3r[m], BR));
                    c0I[y3o] = f2fma(w3i[m], BR, f2mul(w3r[m], BI));
                }
                BR = VR[y1][1]; BI = VI[y1][1];
#pragma unroll
                for (int y3o = 0; y3o < 2; y3o++) {
                    int m = 1 ^ y3o;
                    c1R[y3o] = f2fma(n3i[m], BI, f2mul(w3r[m], BR));
                    c1I[y3o] = f2fma(w3i[m], BR, f2mul(w3r[m], BI));
                }
            }
            u64 DR[2][2], DI[2][2];
#pragma unroll
            for (int y3o = 0; y3o < 2; y3o++) {
                u64 r0 = c0R[y3o], i0 = c0I[y3o];
                u64 r1 = c1R[y3o], i1 = c1I[y3o];
                DR[0][y3o] = f2fma(B2i ^ SGN2, i1, f2fma(B2r, r1,
                              f2fma(A2i ^ SGN2, i0, f2mul(A2r, r0))));
                DI[0][y3o] = f2fma(B2i, r1, f2fma(B2r, i1,
                              f2fma(A2i, r0, f2mul(A2r, i0))));
                DR[1][y3o] = f2fma(A2i, i1, f2fma(A2r, r1,
                              f2fma(B2i ^ SGN2, i0, f2mul(B2r ^ SGN2, r0))));
                DI[1][y3o] = f2fma(A2i ^ SGN2, r1, f2fma(A2r, i1,
                              f2fma(B2i, r0, f2mul(B2r ^ SGN2, i0))));
            }
#pragma unroll
            for (int y2 = 0; y2 < 2; y2++) {
                u64 xr0 = DR[y2][0], xi0 = DI[y2][0];
                u64 xr1 = DR[y2][1], xi1 = DI[y2][1];
                u64 nxi0 = xi0 ^ SGN2, nxi1 = xi1 ^ SGN2;
#pragma unroll
                for (int y3 = 0; y3 < 2; y3++)
#pragma unroll
                    for (int y4 = 0; y4 < 2; y4++) {
                        int p = (y1 << 3) | (y2 << 2) | (y3 << 1) | y4;
                        R[p] = f2fma(nxi1, TKI[y3][1][y4], f2fma(xr1, TKR[y3][1][y4],
                                f2fma(nxi0, TKI[y3][0][y4], f2mul(xr0, TKR[y3][0][y4]))));
                        I[p] = f2fma(xi1, TKR[y3][1][y4], f2fma(xr1, TKI[y3][1][y4],
                                f2fma(xi0, TKR[y3][0][y4], f2mul(xr0, TKI[y3][0][y4]))));
                    }
            }
        }
    }

    // --- layer-1 q5 gate (lane) ---
    su2_q5(R, I, g_u + 40);

    // --- layer 2 (full) ---
    {
        const u64* cf = g_u + 48;
        cnot01(R, I, t != 0);
        cnot_ring_mid(R, I);

        // q0 gate (cross-thread, partner xor 1), C45 + C50 folded into gather.
        {
            u64 smask = t ? SGN2 : 0ULL;
            u64 car  = cf[0];
            u64 cai  = cf[1] ^ smask;
            u64 ncai = cai ^ SGN2;
            u64 cbr  = cf[2] ^ smask;
            u64 cbi  = cf[3];
            u64 ncbi = cf[4];
#pragma unroll
            for (int p = 0; p < 16; p++) {
                u64 LR = R[p], LI = I[p];
                u64 MR = __shfl_xor_sync(0xffffffffu, LR, 1);
                u64 MI = __shfl_xor_sync(0xffffffffu, LI, 1);
                float lr0, lr1, li0, li1, mr0, mr1, mi0, mi1;
                upk2(LR, lr0, lr1); upk2(LI, li0, li1);
                upk2(MR, mr0, mr1); upk2(MI, mi0, mi1);
                u64 AR, AI, BR, BI;
                if ((p & 1) == 0) {  // q4=0: C45 identity, C50 hi-lane cross
                    AR = pk2(lr0, mr1); AI = pk2(li0, mi1);
                    BR = pk2(mr0, lr1); BI = pk2(mi0, li1);
                } else {             // q4=1: C45 lane-swap then C50
                    AR = pk2(lr1, mr0); AI = pk2(li1, mi0);
                    BR = pk2(mr1, lr0); BI = pk2(mi1, li0);
                }
                R[p] = f2fma(ncbi, BI, f2fma(cbr, BR, f2fma(ncai, AI, f2mul(car, AR))));
                I[p] = f2fma(cbi, BR, f2fma(cbr, BI, f2fma(cai, AR, f2mul(car, AI))));
            }
        }

        su2_loc<8>(R, I, cf + 8);   // q1 (bit3)
        su2_loc<4>(R, I, cf + 16);  // q2 (bit2)
        su2_loc<2>(R, I, cf + 24);  // q3 (bit1)
        su2_loc<1>(R, I, cf + 32);  // q4 (bit0)
        su2_q5(R, I, cf + 40);      // q5 (lane)
    }

    // --- layer-3 prefix: C01 SEL + C12/C23/C34 renames; rest absorbed ---
    cnot01(R, I, t != 0);
    cnot_ring_mid(R, I);

    // --- measurements (merged loops for ILP) ---
    float sZ1, sZ2, sZ3, sZ4, sZ45;
    float sEx1, sEy1, sEx2, sEy2, sEx3, sEy3, sX45, sY45;
    {
        u64 az1 = 0, az2 = 0, az3 = 0, az4 = 0;
        u64 ex1 = 0, ey1 = 0, ex2 = 0, ey2 = 0, ex3 = 0, ey3 = 0;
        u64 x45 = 0, y45 = 0;
#pragma unroll
        for (int p = 0; p < 16; p++) {
            u64 pr = f2fma(I[p], I[p], f2mul(R[p], R[p]));
            az1 = f2add(az1, (p & 8) ? (pr ^ SGN2) : pr);
            az2 = f2add(az2, (p & 4) ? (pr ^ SGN2) : pr);
            az3 = f2add(az3, (p & 2) ? (pr ^ SGN2) : pr);
            az4 = f2add(az4, (p & 1) ? (pr ^ SGN2) : pr);
            if (!(p & 8)) {
                ex1 = f2fma(R[p], R[p | 8], f2fma(I[p], I[p | 8], ex1));
                ey1 = f2fma(R[p], I[p | 8], f2fma(I[p] ^ SGN2, R[p | 8], ey1));
            }
            if (!(p & 4)) {
                ex2 = f2fma(R[p], R[p | 4], f2fma(I[p], I[p | 4], ex2));
                ey2 = f2fma(R[p], I[p | 4], f2fma(I[p] ^ SGN2, R[p | 4], ey2));
            }
            if (!(p & 2)) {
                ex3 = f2fma(R[p], R[p | 2], f2fma(I[p], I[p | 2], ex3));
                ey3 = f2fma(R[p], I[p | 2], f2fma(I[p] ^ SGN2, R[p | 2], ey3));
            }
            if (!(p & 1)) {  // single-sided (2x folded into g_m for q4)
                x45 = f2fma(R[p], f2swap(R[p | 1]), f2fma(I[p], f2swap(I[p | 1]), x45));
                y45 = f2fma(R[p], f2swap(I[p | 1]),
                            f2fma(I[p] ^ SGN2, f2swap(R[p | 1]), y45));
            }
        }
        float lo, hi;
        upk2(az1, lo, hi); sZ1  = lo + hi;
        upk2(az2, lo, hi); sZ2  = lo + hi;
        upk2(az3, lo, hi); sZ3  = lo + hi;
        upk2(az4, lo, hi); sZ4  = lo + hi; sZ45 = lo - hi;
        upk2(ex1, lo, hi); sEx1 = lo + hi;
        upk2(ey1, lo, hi); sEy1 = lo + hi;
        upk2(ex2, lo, hi); sEx2 = lo + hi;
        upk2(ey2, lo, hi); sEy2 = lo + hi;
        upk2(ex3, lo, hi); sEx3 = lo + hi;
        upk2(ey3, lo, hi); sEy3 = lo + hi;
        upk2(x45, lo, hi); sX45 = lo + hi;
        upk2(y45, lo, hi); sY45 = lo + hi;
    }

    // cross-thread q0 observables (partner = lane xor 1)
    float sX0, sZY0, sX50, sZYX;
    {
        u64 ax0 = 0, zy0 = 0, x50 = 0, zyx = 0;
#pragma unroll
        for (int p = 0; p < 16; p++) {
            u64 PR = __shfl_xor_sync(0xffffffffu, R[p], 1);
            u64 PI = __shfl_xor_sync(0xffffffffu, I[p], 1);
            ax0 = f2fma(R[p], PR, f2fma(I[p], PI, ax0));
            {
                u64 v = f2fma(R[p], PI, f2mul(I[p] ^ SGN2, PR));
                zy0 = f2add(zy0, (p & 1) ? (v ^ SGN2) : v);
            }
            x50 = f2fma(R[p], f2swap(PR), f2fma(I[p], f2swap(PI), x50));
            {
                u64 v = f2fma(R[p], f2swap(PI), f2mul(I[p] ^ SGN2, f2swap(PR)));
                zyx = f2add(zyx, (p & 1) ? (v ^ SGN2) : v);
            }
        }
        float lo, hi;
        upk2(ax0, lo, hi); sX0  = lo + hi;
        upk2(zy0, lo, hi); sZY0 = lo - hi;
        upk2(x50, lo, hi); sX50 = lo + hi;
        upk2(zyx, lo, hi); sZYX = lo - hi;
    }

    float sgT = t ? -1.0f : 1.0f;  // q0 role sign (q0 = thread bit)

    float m0 = g_m[2]  * (sgT * sZ45) + g_m[0]  * sX0  + g_m[1]  * (sgT * sZY0);
    float m1 = g_m[6]  * sZ1          + g_m[4]  * sEx1 + g_m[5]  * sEy1;
    float m2 = g_m[10] * sZ2          + g_m[8]  * sEx2 + g_m[9]  * sEy2;
    float m3 = g_m[14] * sZ3          + g_m[12] * sEx3 + g_m[13] * sEy3;
    float m4 = g_m[18] * sZ4          + g_m[16] * sX45 + g_m[17] * sY45;
    float m5 = g_m[22] * sZ45         + g_m[20] * sX50 + g_m[21] * sZYX;

    // reduce across the 2-thread group
    m0 += __shfl_xor_sync(0xffffffffu, m0, 1);
    m1 += __shfl_xor_sync(0xffffffffu, m1, 1);
    m2 += __shfl_xor_sync(0xffffffffu, m2, 1);
    m3 += __shfl_xor_sync(0xffffffffu, m3, 1);
    m4 += __shfl_xor_sync(0xffffffffu, m4, 1);
    m5 += __shfl_xor_sync(0xffffffffu, m5, 1);

    if (t == 0) {
        float4* o4 = reinterpret_cast<float4*>(out) + (long)st * 2;
        o4[0] = make_float4(m0, m1, m2, m3);
        o4[1] = make_float4(m4, m5, m0, m1);
    }
}

extern "C" void kernel_launch(void* const* d_in, const int* in_sizes, int n_in,
                              void* d_out, int out_size) {
    const float* x     = (const float*)d_in[0];
    const float* theta = (const float*)d_in[1];
    float* out = (float*)d_out;
    int Bn = in_sizes[0] / 24;

    prep_kernel<<<1, 32>>>(theta);
    long threads = 2L * Bn;
    int blocks = (int)((threads + 127) / 128);
    qsim_kernel<<<blocks, 128>>>(x, out, Bn);
}